// round 8
// baseline (speedup 1.0000x reference)
#include <cuda_runtime.h>
#include <cuda_bf16.h>

#define BB 4
#define HH 16
#define SS 4096
#define DD 64
#define BH (BB*HH)
#define SPLIT 16
#define RR 2
#define PKV (SPLIT*RR)          // 32 kv partials per head
#define PKS (SPLIT*4)           // 64 ksum partials per head
#define ROWS_P1 (SS/SPLIT)      // 256
#define CHUNK 32
#define NCH (ROWS_P1/CHUNK)     // 8
#define P2_TILE 128
#define KEPS 0.001f

typedef unsigned long long ull;

// Scratch (device globals: no allocs allowed)
__device__ float g_kv[BH][PKV][DD * DD];
__device__ float g_ksum[BH][PKS][DD];
__device__ float g_kvf[BH][DD * DD];
__device__ float g_ksumf[BH][DD];

// ---- packed fp32x2 helpers (sm_103a FFMA2 — only via PTX) ----
__device__ __forceinline__ ull ffma2(ull a, ull b, ull c) {
    ull d;
    asm("fma.rn.f32x2 %0, %1, %2, %3;" : "=l"(d) : "l"(a), "l"(b), "l"(c));
    return d;
}
__device__ __forceinline__ ull pack2(float x) {
    ull d;
    asm("mov.b64 %0, {%1, %1};" : "=l"(d) : "f"(x));
    return d;
}
__device__ __forceinline__ ull packf2(float x, float y) {
    ull d;
    asm("mov.b64 %0, {%1, %2};" : "=l"(d) : "f"(x), "f"(y));
    return d;
}
__device__ __forceinline__ float2 unpack2(ull a) {
    float2 r;
    asm("mov.b64 {%0, %1}, %2;" : "=f"(r.x), "=f"(r.y) : "l"(a));
    return r;
}

// ---------------------------------------------------------------------------
// Pass 1: kv[d][e] += k'[r][d]*v[r][e]. k' stored DUPLICATE-PACKED in smem
// ((k,k) ulls, packed once at staging) so the mainloop has ZERO MOVs:
// per row-iter = 2 LDS.128 (kdup) + 2 LDS.128 (v) + 16 FFMA2.
// Tile 4d x 8e, rr=tid>>7 two-way row split -> own partial. CHUNK=32.
// ksum: thread (g4, dks) sums d=dks over rows r%4==g4 via LDS.32 of low half.
// ---------------------------------------------------------------------------
__global__ __launch_bounds__(256, 3) void perf_pass1(
    const float* __restrict__ K,
    const float* __restrict__ V,
    const float* __restrict__ mask)
{
    const int bh = blockIdx.x / SPLIT;
    const int sp = blockIdx.x % SPLIT;
    const int b  = bh / HH;

    const float* Kp = K + (size_t)bh * SS * DD + (size_t)sp * ROWS_P1 * DD;
    const float* Vp = V + (size_t)bh * SS * DD + (size_t)sp * ROWS_P1 * DD;
    const float* Mp = mask + (size_t)b * SS + (size_t)sp * ROWS_P1;

    __shared__ ull   kd[2][CHUNK][DD];   // 32KB duplicate-packed k'
    __shared__ float vs[2][CHUNK][DD];   // 16KB

    const int tid = threadIdx.x;
    const int eq  = tid & 7;
    const int dq  = (tid >> 3) & 15;
    const int rr  = tid >> 7;
    const int g4  = tid >> 6;           // 0..3 ksum row group
    const int dks = tid & 63;
    const int srow = tid >> 4;          // 0..15, stages rows srow, srow+16
    const int scol = (tid & 15) * 4;

    ull acc[4][4];
#pragma unroll
    for (int i = 0; i < 4; i++)
#pragma unroll
        for (int j = 0; j < 4; j++) acc[i][j] = 0ULL;
    float ksacc = 0.f;

    float4 kreg[2], vreg[2];
    float  mreg[2];
#pragma unroll
    for (int t = 0; t < 2; t++) {
        const size_t off = (size_t)(srow + 16 * t) * DD + scol;
        kreg[t] = *reinterpret_cast<const float4*>(&Kp[off]);
        vreg[t] = *reinterpret_cast<const float4*>(&Vp[off]);
        mreg[t] = Mp[srow + 16 * t];
    }

    for (int c = 0; c < NCH; c++) {
        const int buf = c & 1;
#pragma unroll
        for (int t = 0; t < 2; t++) {
            const int row = srow + 16 * t;
            ulonglong2 p0, p1;
            p0.x = pack2((fmaxf(kreg[t].x, 0.f) + KEPS) * mreg[t]);
            p0.y = pack2((fmaxf(kreg[t].y, 0.f) + KEPS) * mreg[t]);
            p1.x = pack2((fmaxf(kreg[t].z, 0.f) + KEPS) * mreg[t]);
            p1.y = pack2((fmaxf(kreg[t].w, 0.f) + KEPS) * mreg[t]);
            *reinterpret_cast<ulonglong2*>(&kd[buf][row][scol])     = p0;
            *reinterpret_cast<ulonglong2*>(&kd[buf][row][scol + 2]) = p1;
            *reinterpret_cast<float4*>(&vs[buf][row][scol]) = vreg[t];
        }
        __syncthreads();

        if (c + 1 < NCH) {
#pragma unroll
            for (int t = 0; t < 2; t++) {
                const size_t off = (size_t)(c + 1) * CHUNK * DD
                                 + (size_t)(srow + 16 * t) * DD + scol;
                kreg[t] = *reinterpret_cast<const float4*>(&Kp[off]);
                vreg[t] = *reinterpret_cast<const float4*>(&Vp[off]);
                mreg[t] = Mp[(c + 1) * CHUNK + srow + 16 * t];
            }
        }

        // ksum: low halves of kd, 8 rows per chunk
        const float* kfp = reinterpret_cast<const float*>(&kd[buf][0][0]);
#pragma unroll
        for (int j = 0; j < 8; j++)
            ksacc += kfp[((j * 4 + g4) * DD + dks) * 2];

#pragma unroll
        for (int r0 = 0; r0 < CHUNK; r0 += RR) {
            const int r = r0 + rr;
            const ulonglong2 k01 = *reinterpret_cast<const ulonglong2*>(&kd[buf][r][dq * 4]);
            const ulonglong2 k23 = *reinterpret_cast<const ulonglong2*>(&kd[buf][r][dq * 4 + 2]);
            const ulonglong2 va  = *reinterpret_cast<const ulonglong2*>(&vs[buf][r][eq * 4]);
            const ulonglong2 vb  = *reinterpret_cast<const ulonglong2*>(&vs[buf][r][eq * 4 + 32]);
            const ull kk[4] = {k01.x, k01.y, k23.x, k23.y};
#pragma unroll
            for (int i = 0; i < 4; i++) {
                acc[i][0] = ffma2(kk[i], va.x, acc[i][0]);
                acc[i][1] = ffma2(kk[i], va.y, acc[i][1]);
                acc[i][2] = ffma2(kk[i], vb.x, acc[i][2]);
                acc[i][3] = ffma2(kk[i], vb.y, acc[i][3]);
            }
        }
    }

    float* kvp = g_kv[bh][(sp << 1) | rr];
#pragma unroll
    for (int i = 0; i < 4; i++) {
        ull* row = reinterpret_cast<ull*>(kvp + (size_t)(dq * 4 + i) * DD);
        row[eq * 2]          = acc[i][0];
        row[eq * 2 + 1]      = acc[i][1];
        row[16 + eq * 2]     = acc[i][2];
        row[16 + eq * 2 + 1] = acc[i][3];
    }
    g_ksum[bh][(sp << 2) | g4][dks] = ksacc;
}

// ---------------------------------------------------------------------------
// Reduce: sum 32 kv partials + 64 ksum partials per head.
// ---------------------------------------------------------------------------
__global__ __launch_bounds__(256) void perf_reduce()
{
    const int bh = blockIdx.x >> 2;
    const int qt = blockIdx.x & 3;
    const int tid = threadIdx.x;
    const int idx = qt * 1024 + tid * 4;

    float4 s = make_float4(0.f, 0.f, 0.f, 0.f);
#pragma unroll
    for (int p = 0; p < PKV; p++) {
        const float4 v = *reinterpret_cast<const float4*>(&g_kv[bh][p][idx]);
        s.x += v.x; s.y += v.y; s.z += v.z; s.w += v.w;
    }
    *reinterpret_cast<float4*>(&g_kvf[bh][idx]) = s;

    if (qt == 0 && tid < DD) {
        float t = 0.f;
#pragma unroll
        for (int p = 0; p < PKS; p++) t += g_ksum[bh][p][tid];
        g_ksumf[bh][tid] = t;
    }
}

// ---------------------------------------------------------------------------
// Pass 2: out[s,e] = (q'[s,:] . kv[:,e]) / (q'[s,:] . ksum), s-pair packed:
//   qt[d][p]  = (q'[2p][d], q'[2p+1][d])   transposed-interleaved, XOR-swizzle
//   kvd[d][e] = (kv[d][e], kv[d][e])       duplicate-packed
//   acc[(s-pair), e] accumulated with FFMA2 — ZERO MOVs in the mainloop.
// Thread tile: 2 s-pairs (4 rows) x 8 e. Per d: 6 LDS + 18 FFMA2.
// ---------------------------------------------------------------------------
__global__ __launch_bounds__(256, 3) void perf_pass2(
    const float* __restrict__ Q,
    float* __restrict__ O)
{
    extern __shared__ ull smu[];
    ull* qtb = smu;                       // [DD][P2_TILE/2] = 32KB
    ull* kvd = smu + DD * (P2_TILE / 2);  // [DD][DD] = 32KB
    ull* ksd = kvd + DD * DD;             // [DD]

    const int bh   = blockIdx.x >> 5;
    const int tile = blockIdx.x & 31;
    const int tid  = threadIdx.x;
    const int eq   = tid & 7;
    const int pq   = tid >> 3;            // 0..31 -> s-pairs 2pq, 2pq+1 (rows 4pq..+3)

    // build duplicate-packed kv and ksum
#pragma unroll
    for (int i = 0; i < 4; i++) {
        const int idx = tid * 4 + i * 1024;
        const float4 v = *reinterpret_cast<const float4*>(&g_kvf[bh][idx]);
        ulonglong2 w0, w1;
        w0.x = pack2(v.x); w0.y = pack2(v.y);
        w1.x = pack2(v.z); w1.y = pack2(v.w);
        *reinterpret_cast<ulonglong2*>(&kvd[idx])     = w0;
        *reinterpret_cast<ulonglong2*>(&kvd[idx + 2]) = w1;
    }
    if (tid < DD) ksd[tid] = pack2(g_ksumf[bh][tid]);

    // stage q transposed-interleaved with XOR swizzle on the pair index:
    // logical pair p of column d stored at qt[d][p ^ (((d>>4)&3)*2)]
    const float* Qp = Q + (size_t)bh * SS * DD + (size_t)tile * P2_TILE * DD;
    float*       Op = O + (size_t)bh * SS * DD + (size_t)tile * P2_TILE * DD;
    {
        const int p  = tid >> 2;            // 0..63: rows 2p, 2p+1
        const int c0 = (tid & 3) * 16;
        const int sx = (tid & 3) * 2;       // == ((c>>4)&3)*2 for all c in block
#pragma unroll
        for (int blk = 0; blk < 4; blk++) {
            const int c = c0 + blk * 4;
            float4 a = *reinterpret_cast<const float4*>(&Qp[(size_t)(2 * p) * DD + c]);
            float4 g = *reinterpret_cast<const float4*>(&Qp[(size_t)(2 * p + 1) * DD + c]);
            a.x = fmaxf(a.x, 0.f) + KEPS; a.y = fmaxf(a.y, 0.f) + KEPS;
            a.z = fmaxf(a.z, 0.f) + KEPS; a.w = fmaxf(a.w, 0.f) + KEPS;
            g.x = fmaxf(g.x, 0.f) + KEPS; g.y = fmaxf(g.y, 0.f) + KEPS;
            g.z = fmaxf(g.z, 0.f) + KEPS; g.w = fmaxf(g.w, 0.f) + KEPS;
            qtb[(c + 0) * (P2_TILE / 2) + (p ^ sx)] = packf2(a.x, g.x);
            qtb[(c + 1) * (P2_TILE / 2) + (p ^ sx)] = packf2(a.y, g.y);
            qtb[(c + 2) * (P2_TILE / 2) + (p ^ sx)] = packf2(a.z, g.z);
            qtb[(c + 3) * (P2_TILE / 2) + (p ^ sx)] = packf2(a.w, g.w);
        }
    }
    __syncthreads();

    ull acc[2][8];
#pragma unroll
    for (int i = 0; i < 2; i++)
#pragma unroll
        for (int j = 0; j < 8; j++) acc[i][j] = 0ULL;
    ull dacc[2] = {0ULL, 0ULL};

#pragma unroll 4
    for (int d = 0; d < DD; d++) {
        const int sx = ((d >> 4) & 3) * 2;
        const ulonglong2 qp = *reinterpret_cast<const ulonglong2*>(
            &qtb[d * (P2_TILE / 2) + ((pq * 2) ^ sx)]);
        const ull ksv = ksd[d];
        dacc[0] = ffma2(qp.x, ksv, dacc[0]);
        dacc[1] = ffma2(qp.y, ksv, dacc[1]);

        const ull* kvrow = &kvd[d * DD];
        const ulonglong2 e01 = *reinterpret_cast<const ulonglong2*>(&kvrow[eq * 4]);
        const ulonglong2 e23 = *reinterpret_cast<const ulonglong2*>(&kvrow[eq * 4 + 2]);
        const ulonglong2 e45 = *reinterpret_cast<const ulonglong2*>(&kvrow[eq * 4 + 32]);
        const ulonglong2 e67 = *reinterpret_cast<const ulonglong2*>(&kvrow[eq * 4 + 34]);
        const ull kve[8] = {e01.x, e01.y, e23.x, e23.y, e45.x, e45.y, e67.x, e67.y};
#pragma unroll
        for (int e = 0; e < 8; e++) {
            acc[0][e] = ffma2(qp.x, kve[e], acc[0][e]);
            acc[1][e] = ffma2(qp.y, kve[e], acc[1][e]);
        }
    }

    // epilogue: acc[i][e] = (out[4pq+2i][e'], out[4pq+2i+1][e'])
    const float2 den0 = unpack2(dacc[0]);
    const float2 den1 = unpack2(dacc[1]);
    const float inv0 = 1.f / den0.x, inv1 = 1.f / den0.y;
    const float inv2 = 1.f / den1.x, inv3 = 1.f / den1.y;

#pragma unroll
    for (int i = 0; i < 2; i++) {
        const float invA = (i == 0) ? inv0 : inv2;
        const float invB = (i == 0) ? inv1 : inv3;
        float2 lo[8];
#pragma unroll
        for (int e = 0; e < 8; e++) lo[e] = unpack2(acc[i][e]);
        const int rowA = 4 * pq + 2 * i;
        const int rowB = rowA + 1;
        float4 a0 = make_float4(lo[0].x * invA, lo[1].x * invA, lo[2].x * invA, lo[3].x * invA);
        float4 a1 = make_float4(lo[4].x * invA, lo[5].x * invA, lo[6].x * invA, lo[7].x * invA);
        float4 b0 = make_float4(lo[0].y * invB, lo[1].y * invB, lo[2].y * invB, lo[3].y * invB);
        float4 b1 = make_float4(lo[4].y * invB, lo[5].y * invB, lo[6].y * invB, lo[7].y * invB);
        *reinterpret_cast<float4*>(&Op[(size_t)rowA * DD + eq * 4])      = a0;
        *reinterpret_cast<float4*>(&Op[(size_t)rowA * DD + eq * 4 + 32]) = a1;
        *reinterpret_cast<float4*>(&Op[(size_t)rowB * DD + eq * 4])      = b0;
        *reinterpret_cast<float4*>(&Op[(size_t)rowB * DD + eq * 4 + 32]) = b1;
    }
}

#define SMEM_P2 ((DD * (P2_TILE / 2) + DD * DD + DD) * (int)sizeof(ull))

extern "C" void kernel_launch(void* const* d_in, const int* in_sizes, int n_in,
                              void* d_out, int out_size)
{
    const float* Q = (const float*)d_in[0];
    const float* K = (const float*)d_in[1];
    const float* V = (const float*)d_in[2];
    const float* M = (const float*)d_in[3];
    float* O = (float*)d_out;

    cudaFuncSetAttribute(perf_pass2, cudaFuncAttributeMaxDynamicSharedMemorySize, SMEM_P2);

    perf_pass1<<<BH * SPLIT, 256>>>(K, V, M);
    perf_reduce<<<BH * 4, 256>>>();
    perf_pass2<<<BH * 32, 256, SMEM_P2>>>(Q, O);
}

// round 10
// speedup vs baseline: 1.2815x; 1.2815x over previous
#include <cuda_runtime.h>
#include <cstdint>

#define BB 4
#define HH 16
#define SS 4096
#define DD 64
#define BH (BB*HH)
#define SPLIT 16
#define ROWS_P1 (SS/SPLIT)   // 256
#define KEPS 0.001f

// Scratch (device globals: no allocs allowed)
__device__ float g_kvp[BH][32][DD * DD];  // partial kv, d-major [d][e]
__device__ float g_ksp[BH][32][DD];       // partial ksum
__device__ float g_kvf[BH][DD * DD];
__device__ float g_ksf[BH][DD];

// ---- tf32 helpers (baseline PTX, sm_80+) ----
__device__ __forceinline__ uint32_t tf32_hi(float x) {
    uint32_t r;
    asm("cvt.rna.tf32.f32 %0, %1;" : "=r"(r) : "f"(x));
    return r;
}
__device__ __forceinline__ void tf32_split(float x, uint32_t& hi, uint32_t& lo) {
    hi = tf32_hi(x);
    lo = tf32_hi(x - __uint_as_float(hi));
}
// D(16x8) += A(16x8,row) * B(8x8,col), tf32 in, fp32 accum
__device__ __forceinline__ void mma8(float* c, const uint32_t* a, const uint32_t* b) {
    asm volatile(
        "mma.sync.aligned.m16n8k8.row.col.f32.tf32.tf32.f32 "
        "{%0,%1,%2,%3}, {%4,%5,%6,%7}, {%8,%9}, {%0,%1,%2,%3};"
        : "+f"(c[0]), "+f"(c[1]), "+f"(c[2]), "+f"(c[3])
        : "r"(a[0]), "r"(a[1]), "r"(a[2]), "r"(a[3]), "r"(b[0]), "r"(b[1]));
}

// smem byte layout pass1: k_s fp32[128][68] @0; v_hi u32[128][72] @34816; v_lo @71680
#define P1_KS_OFF 0
#define P1_VH_OFF 34816
#define P1_VL_OFF 71680
#define SMEM_P1   108544

// ---------------------------------------------------------------------------
// Pass 1: D[d][e] = sum_s k'[s][d] * v[s][e]; ksum via ones-column (n-block 8).
// A = k'^T (reads k_s transposed), B = v (+ones col 64). 256 thr = 8 warps:
// warp-group wg=wid>>2 consumes disjoint 64-row halves of each 128-row chunk
// -> partial index sp*2+wg. 3 tf32 MMAs (hi/lo) per (k-step, n-block).
// ---------------------------------------------------------------------------
__global__ __launch_bounds__(256) void perf_pass1(
    const float* __restrict__ K,
    const float* __restrict__ V,
    const float* __restrict__ mask)
{
    extern __shared__ char smp[];
    float*    k_s  = reinterpret_cast<float*>(smp + P1_KS_OFF);
    uint32_t* v_hi = reinterpret_cast<uint32_t*>(smp + P1_VH_OFF);
    uint32_t* v_lo = reinterpret_cast<uint32_t*>(smp + P1_VL_OFF);

    const int tid  = threadIdx.x;
    const int lane = tid & 31;
    const int wid  = tid >> 5;
    const int wg   = wid >> 2;
    const int m0   = (wid & 3) * 16;
    const int gq   = lane >> 2;   // 0..7
    const int iq   = lane & 3;    // 0..3

    const int bh = blockIdx.x >> 4;
    const int sp = blockIdx.x & 15;
    const int b  = bh / HH;

    const float* Kp = K + (size_t)bh * SS * DD + (size_t)sp * ROWS_P1 * DD;
    const float* Vp = V + (size_t)bh * SS * DD + (size_t)sp * ROWS_P1 * DD;
    const float* Mp = mask + (size_t)b * SS + (size_t)sp * ROWS_P1;

    // ones column (e=64) + zero pad cols 65..71 — persists across chunks
    if (tid < 128) {
        v_hi[tid * 72 + 64] = 0x3F800000u;
        v_lo[tid * 72 + 64] = 0u;
#pragma unroll
        for (int j = 65; j < 72; j++) { v_hi[tid * 72 + j] = 0u; v_lo[tid * 72 + j] = 0u; }
    }

    float C[9][4];
#pragma unroll
    for (int n = 0; n < 9; n++)
#pragma unroll
        for (int j = 0; j < 4; j++) C[n][j] = 0.f;

    const int r  = tid >> 1;
    const int hf = tid & 1;

    for (int it = 0; it < 2; it++) {
        __syncthreads();
        // stage 128 rows: k' fp32 (featurized+masked), v split hi/lo
        {
            const float* kr = Kp + (size_t)(it * 128 + r) * DD + hf * 32;
            const float* vr = Vp + (size_t)(it * 128 + r) * DD + hf * 32;
            const float  mk = Mp[it * 128 + r];
#pragma unroll
            for (int j = 0; j < 32; j += 4) {
                float4 kk = *reinterpret_cast<const float4*>(kr + j);
                kk.x = (fmaxf(kk.x, 0.f) + KEPS) * mk;
                kk.y = (fmaxf(kk.y, 0.f) + KEPS) * mk;
                kk.z = (fmaxf(kk.z, 0.f) + KEPS) * mk;
                kk.w = (fmaxf(kk.w, 0.f) + KEPS) * mk;
                *reinterpret_cast<float4*>(&k_s[r * 68 + hf * 32 + j]) = kk;

                const float4 vv = *reinterpret_cast<const float4*>(vr + j);
                uint4 uh, ul;
                tf32_split(vv.x, uh.x, ul.x);
                tf32_split(vv.y, uh.y, ul.y);
                tf32_split(vv.z, uh.z, ul.z);
                tf32_split(vv.w, uh.w, ul.w);
                *reinterpret_cast<uint4*>(&v_hi[r * 72 + hf * 32 + j]) = uh;
                *reinterpret_cast<uint4*>(&v_lo[r * 72 + hf * 32 + j]) = ul;
            }
        }
        __syncthreads();

        const int sbase = wg * 64;
#pragma unroll
        for (int ks = 0; ks < 8; ks++) {
            const int k0 = sbase + ks * 8;
            // A = k'^T: A[d][s] = k_s[s][d]
            float af[4];
            af[0] = k_s[(k0 + iq) * 68 + m0 + gq];
            af[1] = k_s[(k0 + iq) * 68 + m0 + gq + 8];
            af[2] = k_s[(k0 + iq + 4) * 68 + m0 + gq];
            af[3] = k_s[(k0 + iq + 4) * 68 + m0 + gq + 8];
            uint32_t ah[4], al[4];
#pragma unroll
            for (int j = 0; j < 4; j++) tf32_split(af[j], ah[j], al[j]);

#pragma unroll
            for (int nb = 0; nb < 9; nb++) {
                uint32_t bhr[2], blr[2];
                bhr[0] = v_hi[(k0 + iq) * 72 + nb * 8 + gq];
                bhr[1] = v_hi[(k0 + iq + 4) * 72 + nb * 8 + gq];
                blr[0] = v_lo[(k0 + iq) * 72 + nb * 8 + gq];
                blr[1] = v_lo[(k0 + iq + 4) * 72 + nb * 8 + gq];
                mma8(C[nb], ah, bhr);
                mma8(C[nb], ah, blr);
                mma8(C[nb], al, bhr);
            }
        }
    }

    // epilogue: D rows d = m0+gq, m0+gq+8; cols nb*8 + 2iq(+1)
    const int ps = sp * 2 + wg;
    const int d0 = m0 + gq, d1 = m0 + gq + 8;
    float* out = g_kvp[bh][ps];
#pragma unroll
    for (int nb = 0; nb < 8; nb++) {
        float2 w0 = make_float2(C[nb][0], C[nb][1]);
        float2 w1 = make_float2(C[nb][2], C[nb][3]);
        *reinterpret_cast<float2*>(&out[d0 * 64 + nb * 8 + 2 * iq]) = w0;
        *reinterpret_cast<float2*>(&out[d1 * 64 + nb * 8 + 2 * iq]) = w1;
    }
    if (iq == 0) {   // col 64 = ksum
        g_ksp[bh][ps][d0] = C[8][0];
        g_ksp[bh][ps][d1] = C[8][2];
    }
}

// ---------------------------------------------------------------------------
// Reduce: sum 32 kv partials + 32 ksum partials per head.
// ---------------------------------------------------------------------------
__global__ __launch_bounds__(256) void perf_reduce()
{
    const int bh = blockIdx.x >> 2;
    const int qt = blockIdx.x & 3;
    const int tid = threadIdx.x;
    const int idx = qt * 1024 + tid * 4;

    float4 s = make_float4(0.f, 0.f, 0.f, 0.f);
#pragma unroll
    for (int p = 0; p < 32; p++) {
        const float4 v = *reinterpret_cast<const float4*>(&g_kvp[bh][p][idx]);
        s.x += v.x; s.y += v.y; s.z += v.z; s.w += v.w;
    }
    *reinterpret_cast<float4*>(&g_kvf[bh][idx]) = s;

    if (qt == 0 && tid < DD) {
        float t = 0.f;
#pragma unroll
        for (int p = 0; p < 32; p++) t += g_ksp[bh][p][tid];
        g_ksf[bh][tid] = t;
    }
}

// smem byte layout pass2: q_s fp32[128][68] @0; kv_hi u32[64][72] @34816; kv_lo @53248
#define P2_QS_OFF 0
#define P2_KH_OFF 34816
#define P2_KL_OFF 53248
#define SMEM_P2   71680

// ---------------------------------------------------------------------------
// Pass 2: out[s][e] = (q'[s,:] . kv[:,e]) / (q'[s,:] . ksum)
// A = q' (row-major), B = kv hi/lo with ksum hi/lo embedded as col 64.
// 8 warps x m16 = 128-row tile; denominator from n-block 8 via shfl.
// ---------------------------------------------------------------------------
__global__ __launch_bounds__(256) void perf_pass2(
    const float* __restrict__ Q,
    float* __restrict__ O)
{
    extern __shared__ char smp[];
    float*    q_s   = reinterpret_cast<float*>(smp + P2_QS_OFF);
    uint32_t* kv_hi = reinterpret_cast<uint32_t*>(smp + P2_KH_OFF);
    uint32_t* kv_lo = reinterpret_cast<uint32_t*>(smp + P2_KL_OFF);

    const int tid  = threadIdx.x;
    const int lane = tid & 31;
    const int wid  = tid >> 5;
    const int m0   = wid * 16;
    const int gq   = lane >> 2;
    const int iq   = lane & 3;

    const int bh   = blockIdx.x >> 5;
    const int tile = blockIdx.x & 31;

    // stage kv hi/lo (+ksum col 64, zero pad 65..71)
    {
        const int d  = tid >> 2;
        const int c0 = (tid & 3) * 16;
        const float* src = &g_kvf[bh][(size_t)d * 64 + c0];
#pragma unroll
        for (int j = 0; j < 16; j += 4) {
            const float4 v = *reinterpret_cast<const float4*>(src + j);
            uint4 uh, ul;
            tf32_split(v.x, uh.x, ul.x);
            tf32_split(v.y, uh.y, ul.y);
            tf32_split(v.z, uh.z, ul.z);
            tf32_split(v.w, uh.w, ul.w);
            *reinterpret_cast<uint4*>(&kv_hi[d * 72 + c0 + j]) = uh;
            *reinterpret_cast<uint4*>(&kv_lo[d * 72 + c0 + j]) = ul;
        }
        if ((tid & 3) == 3) {
            uint32_t h, l;
            tf32_split(g_ksf[bh][d], h, l);
            kv_hi[d * 72 + 64] = h;
            kv_lo[d * 72 + 64] = l;
#pragma unroll
            for (int j = 65; j < 72; j++) { kv_hi[d * 72 + j] = 0u; kv_lo[d * 72 + j] = 0u; }
        }
    }

    // stage q' fp32
    const float* Qp = Q + (size_t)bh * SS * DD + (size_t)tile * 128 * DD;
    float*       Op = O + (size_t)bh * SS * DD + (size_t)tile * 128 * DD;
    {
        const int r  = tid >> 1;
        const int hf = tid & 1;
        const float* qr = Qp + (size_t)r * DD + hf * 32;
#pragma unroll
        for (int j = 0; j < 32; j += 4) {
            float4 v = *reinterpret_cast<const float4*>(qr + j);
            v.x = fmaxf(v.x, 0.f) + KEPS;
            v.y = fmaxf(v.y, 0.f) + KEPS;
            v.z = fmaxf(v.z, 0.f) + KEPS;
            v.w = fmaxf(v.w, 0.f) + KEPS;
            *reinterpret_cast<float4*>(&q_s[r * 68 + hf * 32 + j]) = v;
        }
    }
    __syncthreads();

    float C[9][4];
#pragma unroll
    for (int n = 0; n < 9; n++)
#pragma unroll
        for (int j = 0; j < 4; j++) C[n][j] = 0.f;

#pragma unroll
    for (int ks = 0; ks < 8; ks++) {
        const int k0 = ks * 8;
        float af[4];
        af[0] = q_s[(m0 + gq) * 68 + k0 + iq];
        af[1] = q_s[(m0 + gq + 8) * 68 + k0 + iq];
        af[2] = q_s[(m0 + gq) * 68 + k0 + iq + 4];
        af[3] = q_s[(m0 + gq + 8) * 68 + k0 + iq + 4];
        uint32_t ah[4], al[4];
#pragma unroll
        for (int j = 0; j < 4; j++) tf32_split(af[j], ah[j], al[j]);

#pragma unroll
        for (int nb = 0; nb < 9; nb++) {
            uint32_t bhr[2], blr[2];
            bhr[0] = kv_hi[(k0 + iq) * 72 + nb * 8 + gq];
            bhr[1] = kv_hi[(k0 + iq + 4) * 72 + nb * 8 + gq];
            blr[0] = kv_lo[(k0 + iq) * 72 + nb * 8 + gq];
            blr[1] = kv_lo[(k0 + iq + 4) * 72 + nb * 8 + gq];
            mma8(C[nb], ah, bhr);
            mma8(C[nb], ah, blr);
            mma8(C[nb], al, bhr);
        }
    }

    // denominator = col 64 (n-block 8), held by iq==0 lanes; broadcast in quad
    float den0 = __shfl_sync(0xFFFFFFFFu, C[8][0], lane & 28);
    float den1 = __shfl_sync(0xFFFFFFFFu, C[8][2], lane & 28);
    const float inv0 = 1.f / den0;
    const float inv1 = 1.f / den1;

    const int row0 = m0 + gq, row1 = m0 + gq + 8;
#pragma unroll
    for (int nb = 0; nb < 8; nb++) {
        float2 w0 = make_float2(C[nb][0] * inv0, C[nb][1] * inv0);
        float2 w1 = make_float2(C[nb][2] * inv1, C[nb][3] * inv1);
        *reinterpret_cast<float2*>(&Op[(size_t)row0 * 64 + nb * 8 + 2 * iq]) = w0;
        *reinterpret_cast<float2*>(&Op[(size_t)row1 * 64 + nb * 8 + 2 * iq]) = w1;
    }
}

extern "C" void kernel_launch(void* const* d_in, const int* in_sizes, int n_in,
                              void* d_out, int out_size)
{
    const float* Q = (const float*)d_in[0];
    const float* K = (const float*)d_in[1];
    const float* V = (const float*)d_in[2];
    const float* M = (const float*)d_in[3];
    float* O = (float*)d_out;

    cudaFuncSetAttribute(perf_pass1, cudaFuncAttributeMaxDynamicSharedMemorySize, SMEM_P1);
    cudaFuncSetAttribute(perf_pass2, cudaFuncAttributeMaxDynamicSharedMemorySize, SMEM_P2);

    perf_pass1<<<BH * SPLIT, 256, SMEM_P1>>>(K, V, M);
    perf_reduce<<<BH * 4, 256>>>();
    perf_pass2<<<BH * 32, 256, SMEM_P2>>>(Q, O);
}